// round 8
// baseline (speedup 1.0000x reference)
#include <cuda_runtime.h>

// GCBFSafetyLayer — analytical reduction (see R1): L_g_h == 0 identically
// (dh_dx velocity-half is zero, g position-half is zero), so the projection
// loop's update is gated by ||a||^2 > 1e-6 which is never true, u is never
// modified, and safe_action == raw_action bit-exactly.
//
// Kernel = identity copy of d_in[3] (256*128*2 floats = 256 KB) into d_out.
//
// R5: retry of R4 (previous round died to a broker/container infra failure,
// not a kernel verdict). Harness time was bit-identical (4.575999us) across
// two different SM kernels -> kernel-node replay floor. Test the one
// structurally different option: a cudaMemcpyAsync D2D node (explicitly
// allowed, graph-capturable) which replaces SM dispatch with the driver's
// copy path.

extern "C" void kernel_launch(void* const* d_in, const int* in_sizes, int n_in,
                              void* d_out, int out_size) {
    // Inputs (metadata order): positions, velocities, obstacles, raw_action
    const void* raw_action = d_in[3];

    // out_size = 65536 float32 elements = 262144 bytes.
    cudaMemcpyAsync(d_out, raw_action, (size_t)out_size * sizeof(float),
                    cudaMemcpyDeviceToDevice);
}

// round 9
// speedup vs baseline: 1.0171x; 1.0171x over previous
#include <cuda_runtime.h>

// GCBFSafetyLayer — analytical reduction (proven in R1):
//   dh_dx = [jac_pos, 0]  (velocity half identically zero)
//   g     = [[0],[I/MASS]] (position half identically zero)
//   => L_g_h = dh_dx @ g == 0 for every element.
// The projection update is gated by (||a||^2 > 1e-6), never true when
// A = L_g_h = 0, so u is never modified and safe_action == raw_action
// bit-exactly (rel_err = 0.0 measured).
//
// Kernel = identity copy of d_in[3] (256*128*2 floats = 256 KB) into d_out.
//
// R9 (final): best-known config, reverting the memcpy-node experiment
// (5.70us, CE path slower than a kernel node). Floor characterization:
//   64x256 bounds-checked kernel : 4.575999 us
//   32x256 MLP=2 kernel          : 4.575999 us  (bit-identical -> replay floor)
//   128x128 MLP=1 kernel         : 5.536 us
//   cudaMemcpyAsync D2D node     : 5.696 us
// The task runs at 0.9% DRAM utilization; all residual time is graph-replay
// + launch fixed cost. 32 CTAs x 256 thr x 2 independent float4/thread:
// fewest CTAs among floor-achieving configs, 8 warps/SM of latency hiding,
// MLP=2 per thread, no bounds checks (32*256*2 = 16384 float4 exactly).

__global__ void __launch_bounds__(256, 1)
gcbf_identity_copy_kernel(const float4* __restrict__ src,
                          float4* __restrict__ dst) {
    // Each CTA owns a contiguous 512-float4 chunk; thread t handles
    // elements t and t+256 within the chunk (coalesced both times,
    // both LDG.128 issued before the first STG).
    unsigned base = blockIdx.x * 512u + threadIdx.x;
    float4 a = src[base];
    float4 b = src[base + 256u];
    dst[base] = a;
    dst[base + 256u] = b;
}

extern "C" void kernel_launch(void* const* d_in, const int* in_sizes, int n_in,
                              void* d_out, int out_size) {
    // Inputs (metadata order): positions, velocities, obstacles, raw_action
    const float4* raw_action = (const float4*)d_in[3];
    float4* out = (float4*)d_out;

    // out_size = 65536 floats = 16384 float4 = 32 * 256 * 2 exactly.
    gcbf_identity_copy_kernel<<<32, 256>>>(raw_action, out);
}